// round 14
// baseline (speedup 1.0000x reference)
#include <cuda_runtime.h>
#include <cuda_bf16.h>
#include <cuda_fp16.h>

// ---------------------------------------------------------------------------
// PointerNet additive attention, B=4, Te=Td=512, E=256, D+E=512, H=64.
// out[b,d,t] = softmax_t( sum_h w2[h]*tanh(dec_t[b,d,h] + ctx_t[b,t,h]) )
// (b2 cancels in softmax.)
//
// Kernel A: projections with packed dual-FP32 FMA (fma.rn.f32x2). ctx output
//           stored as PACKED f16 h-pairs [b][hp][t] (hp = h/2) for kernel B.
// Kernel B: f16x2 tanh hot loop with SHORT dependency chains:
//           HADD2 -> TANH2 (1 MUFU / 2 elems) -> cvt f16x2->f32x2 ->
//           fma.rn.f32x2 into packed f32 accumulators (w2 pre-packed pairs).
//           MUFU floor halves to 4 cyc/elem if tanh.approx.f16x2 is 1-slot.
// ---------------------------------------------------------------------------

#define LOG2E 1.4426950408889634f

// scratch (device globals: allocation-free)
__device__ __half2 g_ctxTh[4 * 32 * 512];   // [(b*32+hp)*512 + t]
__device__ float   g_decS[4 * 512 * 64];    // [b*Td+d][h]

typedef unsigned long long ull;

// ---- packed helpers ----
__device__ __forceinline__ ull pack2(float v) {
    ull r; asm("mov.b64 %0, {%1, %1};" : "=l"(r) : "f"(v)); return r;
}
__device__ __forceinline__ void fma2(ull& d, ull a, ull b) {
    asm("fma.rn.f32x2 %0, %1, %2, %0;" : "+l"(d) : "l"(a), "l"(b));
}
__device__ __forceinline__ void add2(ull& d, ull a) {
    asm("add.rn.f32x2 %0, %0, %1;" : "+l"(d) : "l"(a));
}
__device__ __forceinline__ float2 unpack2(ull v) {
    float2 f; asm("mov.b64 {%0, %1}, %2;" : "=f"(f.x), "=f"(f.y) : "l"(v));
    return f;
}
__device__ __forceinline__ __half2 htanh2(__half2 x) {
    __half2 y;
    asm("tanh.approx.f16x2 %0, %1;"
        : "=r"(*reinterpret_cast<unsigned*>(&y))
        : "r"(*reinterpret_cast<const unsigned*>(&x)));
    return y;
}
// f16x2 -> packed f32x2 (two F2F; movs resolved by ptxas reg allocation)
__device__ __forceinline__ ull h2f2(__half2 h) {
    ull r;
    asm("{\n\t"
        ".reg .b16 lo, hi;\n\t"
        ".reg .f32 f0, f1;\n\t"
        "mov.b32 {lo, hi}, %1;\n\t"
        "cvt.f32.f16 f0, lo;\n\t"
        "cvt.f32.f16 f1, hi;\n\t"
        "mov.b64 %0, {f0, f1};\n\t"
        "}" : "=l"(r) : "r"(*reinterpret_cast<const unsigned*>(&h)));
    return r;
}
__device__ __forceinline__ float ex2_approx(float x) {
    float y; asm("ex2.approx.f32 %0, %1;" : "=f"(y) : "f"(x)); return y;
}

// ---------------------------------------------------------------------------
// Kernel A mainloop (R13 FFMA2 version), rows R x depth E, R*E = 4096.
// ---------------------------------------------------------------------------
template<int R, int E, bool IS_CTX>
__device__ __forceinline__ void projA(
    float* buf, const float* __restrict__ X, const float* __restrict__ W,
    const float* __restrict__ bias, int r0)
{
    const int tid  = threadIdx.x;
    const int wid  = tid >> 5;
    const int lane = tid & 31;
    const int hl   = (lane & 15) << 2;            // h-quad base
    const int half = lane >> 4;                   // e-subrange selector

    {
        float4* buf4 = reinterpret_cast<float4*>(buf);
        const float4* src = reinterpret_cast<const float4*>(X)
                          + (size_t)r0 * (E >> 2);
        #pragma unroll
        for (int i = tid; i < 1024; i += 256)
            buf4[i] = src[i];
    }
    __syncthreads();

    ull acc[R][2];
    #pragma unroll
    for (int r = 0; r < R; r++) { acc[r][0] = 0ull; acc[r][1] = 0ull; }

    const int ESUB = E >> 4;
    const int e0 = (wid * 2 + half) * ESUB;
    const float* wptr = W + (size_t)e0 * 64 + hl;

    #pragma unroll 1
    for (int ec = 0; ec < ESUB; ec += 4) {
        ulonglong2 w0 = *reinterpret_cast<const ulonglong2*>(wptr + (ec + 0) * 64);
        ulonglong2 w1 = *reinterpret_cast<const ulonglong2*>(wptr + (ec + 1) * 64);
        ulonglong2 w2v = *reinterpret_cast<const ulonglong2*>(wptr + (ec + 2) * 64);
        ulonglong2 w3 = *reinterpret_cast<const ulonglong2*>(wptr + (ec + 3) * 64);
        #pragma unroll
        for (int r = 0; r < R; r++) {
            float4 x = *reinterpret_cast<const float4*>(&buf[r * E + e0 + ec]);
            ull xx;
            xx = pack2(x.x); fma2(acc[r][0], xx, w0.x); fma2(acc[r][1], xx, w0.y);
            xx = pack2(x.y); fma2(acc[r][0], xx, w1.x); fma2(acc[r][1], xx, w1.y);
            xx = pack2(x.z); fma2(acc[r][0], xx, w2v.x); fma2(acc[r][1], xx, w2v.y);
            xx = pack2(x.w); fma2(acc[r][0], xx, w3.x); fma2(acc[r][1], xx, w3.y);
        }
    }

    #pragma unroll
    for (int r = 0; r < R; r++) {
        ull o0 = __shfl_xor_sync(0xffffffffu, acc[r][0], 16);
        ull o1 = __shfl_xor_sync(0xffffffffu, acc[r][1], 16);
        add2(acc[r][0], o0);
        add2(acc[r][1], o1);
    }

    __syncthreads();
    if (half == 0) {
        #pragma unroll
        for (int r = 0; r < R; r++)
            *reinterpret_cast<ulonglong2*>(&buf[wid * 1024 + r * 64 + hl]) =
                make_ulonglong2(acc[r][0], acc[r][1]);
    }
    __syncthreads();

    if (tid < R * 16) {
        const int o = tid * 4;
        const int r = o >> 6;
        const int h = o & 63;
        float4 s = make_float4(0.f, 0.f, 0.f, 0.f);
        #pragma unroll
        for (int w = 0; w < 8; w++) {
            float4 p = *reinterpret_cast<const float4*>(&buf[w * 1024 + o]);
            s.x += p.x; s.y += p.y; s.z += p.z; s.w += p.w;
        }
        float4 bv = *reinterpret_cast<const float4*>(bias + h);
        s.x += bv.x; s.y += bv.y; s.z += bv.z; s.w += bv.w;

        const int row = r0 + r;
        if (IS_CTX) {
            const int b = row >> 9, t = row & 511;
            const int hp = h >> 1;
            __half2* dst = g_ctxTh + ((size_t)((b << 5) + hp)) * 512 + t;
            dst[0]   = __floats2half2_rn(s.x, s.y);
            dst[512] = __floats2half2_rn(s.z, s.w);
        } else {
            *reinterpret_cast<float4*>(&g_decS[(size_t)row * 64 + h]) = s;
        }
    }
}

__global__ __launch_bounds__(256) void kernelA(
    const float* __restrict__ ctx,   // [4,512,256]
    const float* __restrict__ dec,   // [4,512,512]
    const float* __restrict__ W1i,   // [256,64]
    const float* __restrict__ b1i,   // [64]
    const float* __restrict__ W1h,   // [512,64]
    const float* __restrict__ b1h)   // [64]
{
    __shared__ __align__(16) float buf[8192];
    if (blockIdx.x < 128) {
        projA<16, 256, true >(buf, ctx, W1i, b1i, blockIdx.x * 16);
    } else {
        projA< 8, 512, false>(buf, dec, W1h, b1h, (blockIdx.x - 128) * 8);
    }
}

// ---------------------------------------------------------------------------
// Kernel B: f16x2 tanh-score + softmax.
// grid = 296 (4 batches x 74 d-tiles of 7), 512 threads, 2 blocks/SM.
// Per (h-pair, d): HADD2 + TANH2 + 2 F2F + FFMA2(f32x2 acc).
// ---------------------------------------------------------------------------
__global__ __launch_bounds__(512) void kernelB(
    const float* __restrict__ w2,    // [64]
    float* __restrict__ out)         // [4,512,512]
{
    __shared__ __align__(8)  __half2 dec_sh[7 * 32];  // 7 rows x 32 h-pairs
    __shared__ __align__(16) float2  w2f2[32];        // packed w2 pairs * log2e
    __shared__ float red[7 * 16];
    __shared__ float inv_sh[7];

    const int tid = threadIdx.x;
    const int b   = blockIdx.x / 74;
    const int ti  = blockIdx.x % 74;
    const int d0  = ti * 7;

    // fill dec tile (converted to f16 pairs; zero past batch end) + w2 pairs
    if (tid < 224) {
        int r = tid >> 5, hp = tid & 31;
        float2 v = (d0 + r < 512)
            ? reinterpret_cast<const float2*>(g_decS + ((size_t)(b << 9) + d0 + r) * 64)[hp]
            : make_float2(0.f, 0.f);
        dec_sh[tid] = __floats2half2_rn(v.x, v.y);
    } else if (tid >= 480) {
        int i = tid - 480;
        w2f2[i] = make_float2(w2[2 * i] * LOG2E, w2[2 * i + 1] * LOG2E);
    }
    __syncthreads();

    const __half2* cptr = g_ctxTh + (size_t)(b << 5) * 512 + tid;

    ull acc2[7];
    #pragma unroll
    for (int d = 0; d < 7; d++) acc2[d] = 0ull;

    // prime with pairs hp=0,1
    __half2 c0 = cptr[0 * 512];
    __half2 c1 = cptr[1 * 512];

    #pragma unroll 1
    for (int hp = 0; hp < 32; hp += 2) {
        // prefetch next two pairs (wrap &31 on last iter: in-bounds, unused)
        const int hn = (hp + 2) & 31;
        __half2 n0 = cptr[(hn + 0) * 512];
        __half2 n1 = cptr[(hn + 1) * 512];

        ulonglong2 wp = *reinterpret_cast<const ulonglong2*>(&w2f2[hp]);
        #pragma unroll
        for (int d = 0; d < 7; d++) {
            uint2 dd = *reinterpret_cast<const uint2*>(&dec_sh[d * 32 + hp]);
            __half2 a0 = __hadd2(*reinterpret_cast<__half2*>(&dd.x), c0);
            __half2 a1 = __hadd2(*reinterpret_cast<__half2*>(&dd.y), c1);
            ull f0 = h2f2(htanh2(a0));
            ull f1 = h2f2(htanh2(a1));
            fma2(acc2[d], f0, wp.x);
            fma2(acc2[d], f1, wp.y);
        }
        c0 = n0; c1 = n1;
    }

    // softmax over t (scores in log2 domain via scaled w2; bounded by
    // sum|w2|*log2e ~ 9 => no max-shift needed)
    const int wid = tid >> 5, lane = tid & 31;
    float ex[7];
    #pragma unroll
    for (int d = 0; d < 7; d++) {
        float2 s2 = unpack2(acc2[d]);
        float e = ex2_approx(s2.x + s2.y);
        ex[d] = e;
        float s = e;
        #pragma unroll
        for (int off = 16; off; off >>= 1)
            s += __shfl_xor_sync(0xffffffffu, s, off);
        if (lane == 0) red[d * 16 + wid] = s;
    }
    __syncthreads();
    if (wid < 7) {
        float v = (lane < 16) ? red[wid * 16 + lane] : 0.f;
        #pragma unroll
        for (int off = 8; off; off >>= 1)
            v += __shfl_xor_sync(0xffffffffu, v, off);
        if (lane == 0) inv_sh[wid] = 1.0f / v;
    }
    __syncthreads();
    #pragma unroll
    for (int d = 0; d < 7; d++) {
        if (d0 + d < 512)
            out[((size_t)(b << 9) + d0 + d) * 512 + tid] = ex[d] * inv_sh[d];
    }
}

// ---------------------------------------------------------------------------
extern "C" void kernel_launch(void* const* d_in, const int* in_sizes, int n_in,
                              void* d_out, int out_size)
{
    const float* ctx  = (const float*)d_in[0];
    const float* dec  = (const float*)d_in[1];
    const float* W1i  = (const float*)d_in[2];
    const float* b1i  = (const float*)d_in[3];
    const float* W1h  = (const float*)d_in[4];
    const float* b1h  = (const float*)d_in[5];
    const float* w2   = (const float*)d_in[6];
    float* out = (float*)d_out;

    kernelA<<<384, 256>>>(ctx, dec, W1i, b1i, W1h, b1h);
    kernelB<<<296, 512>>>(w2, out);
}

// round 15
// speedup vs baseline: 1.0010x; 1.0010x over previous
#include <cuda_runtime.h>
#include <cuda_bf16.h>

// ---------------------------------------------------------------------------
// PointerNet additive attention, B=4, Te=Td=512, E=256, D+E=512, H=64.
// out[b,d,t] = softmax_t( sum_h w2[h]*tanh(dec_t[b,d,h] + ctx_t[b,t,h]) )
// (b2 cancels in softmax.)
//
// Kernel A: 384 EQUAL blocks (16 rows x 256 e-range x 64 h = 262K FMA each):
//   [0,128):   ctx rows,            W1i[0:256]   -> g_ctxT (transposed)
//   [128,256): dec rows, e 0..255,  W1h[0:256]   -> g_decS0 (+bias)
//   [256,384): dec rows, e 256..511,W1h[256:512] -> g_decS1
//   Split-E halves dec weight re-reads (40MB -> 24MB L2 traffic) and makes
//   every block equal work (balanced 2.6 blocks/SM). FFMA2 packed math.
// Kernel B: R13's measured-at-MUFU-floor tanh/softmax (20.9us), prologue
//   sums g_decS0 + g_decS1 when filling dec_sh.
// ---------------------------------------------------------------------------

#define LOG2E 1.4426950408889634f

// scratch (device globals: allocation-free)
__device__ float g_ctxT[4 * 64 * 512];    // [b][h][t]
__device__ float g_decS0[4 * 512 * 64];   // dec proj, e 0..255  (+bias)
__device__ float g_decS1[4 * 512 * 64];   // dec proj, e 256..511

typedef unsigned long long ull;

// ---- packed f32x2 helpers ----
__device__ __forceinline__ ull pack2(float v) {
    ull r; asm("mov.b64 %0, {%1, %1};" : "=l"(r) : "f"(v)); return r;
}
__device__ __forceinline__ void fma2(ull& d, ull a, ull b) {
    asm("fma.rn.f32x2 %0, %1, %2, %0;" : "+l"(d) : "l"(a), "l"(b));
}
__device__ __forceinline__ void add2(ull& d, ull a) {
    asm("add.rn.f32x2 %0, %0, %1;" : "+l"(d) : "l"(a));
}
__device__ __forceinline__ float ex2_approx(float x) {
    float y; asm("ex2.approx.f32 %0, %1;" : "=f"(y) : "f"(x)); return y;
}
__device__ __forceinline__ float tanh_approx(float x) {
    float y; asm("tanh.approx.f32 %0, %1;" : "=f"(y) : "f"(x)); return y;
}

// ---------------------------------------------------------------------------
// Kernel A: 384 blocks x 256 threads, each 16 rows x 256 e-range.
// 8 warps x 2 half-warps = 16 e-subranges of 16; lane owns an h-quad
// (two packed f32x2 accumulators per row).
// ---------------------------------------------------------------------------
__global__ __launch_bounds__(256) void kernelA(
    const float* __restrict__ ctx,   // [4,512,256]
    const float* __restrict__ dec,   // [4,512,512]
    const float* __restrict__ W1i,   // [256,64]
    const float* __restrict__ b1i,   // [64]
    const float* __restrict__ W1h,   // [512,64]
    const float* __restrict__ b1h)   // [64]
{
    __shared__ __align__(16) float buf[8192];     // 16KB tile, then partials

    const int tid  = threadIdx.x;
    const int wid  = tid >> 5;
    const int lane = tid & 31;
    const int hl   = (lane & 15) << 2;            // h-quad base
    const int half = lane >> 4;                   // e-subrange selector
    const int bi   = blockIdx.x;

    const int mode = bi >> 7;                     // 0 ctx, 1 dec-lo, 2 dec-hi
    const int r0   = (bi & 127) * 16;
    const float* X    = (mode == 0) ? ctx : (dec + (mode == 2 ? 256 : 0));
    const float* W    = (mode == 0) ? W1i : (W1h + (mode == 2 ? 256 * 64 : 0));
    const int xstride4 = (mode == 0) ? 64 : 128;  // row stride in float4

    // ---- load x tile [16][256] (gathers e-half for dec) ----
    {
        float4* buf4 = reinterpret_cast<float4*>(buf);
        const float4* src = reinterpret_cast<const float4*>(X);
        #pragma unroll
        for (int i = tid; i < 1024; i += 256) {
            int r = i >> 6, c = i & 63;
            buf4[i] = src[(size_t)(r0 + r) * xstride4 + c];
        }
    }
    __syncthreads();

    // ---- mainloop: packed dual-fp32 FMA ----
    ull acc[16][2];
    #pragma unroll
    for (int r = 0; r < 16; r++) { acc[r][0] = 0ull; acc[r][1] = 0ull; }

    const int e0 = (wid * 2 + half) * 16;         // 16 subranges of 16 e
    const float* wptr = W + (size_t)e0 * 64 + hl;

    #pragma unroll 1
    for (int ec = 0; ec < 16; ec += 4) {
        ulonglong2 w0 = *reinterpret_cast<const ulonglong2*>(wptr + (ec + 0) * 64);
        ulonglong2 w1 = *reinterpret_cast<const ulonglong2*>(wptr + (ec + 1) * 64);
        ulonglong2 w2v = *reinterpret_cast<const ulonglong2*>(wptr + (ec + 2) * 64);
        ulonglong2 w3 = *reinterpret_cast<const ulonglong2*>(wptr + (ec + 3) * 64);
        #pragma unroll
        for (int r = 0; r < 16; r++) {
            float4 x = *reinterpret_cast<const float4*>(&buf[r * 256 + e0 + ec]);
            ull xx;
            xx = pack2(x.x); fma2(acc[r][0], xx, w0.x); fma2(acc[r][1], xx, w0.y);
            xx = pack2(x.y); fma2(acc[r][0], xx, w1.x); fma2(acc[r][1], xx, w1.y);
            xx = pack2(x.z); fma2(acc[r][0], xx, w2v.x); fma2(acc[r][1], xx, w2v.y);
            xx = pack2(x.w); fma2(acc[r][0], xx, w3.x); fma2(acc[r][1], xx, w3.y);
        }
    }

    // ---- combine half-warps (same h-quad, adjacent e-subranges) ----
    #pragma unroll
    for (int r = 0; r < 16; r++) {
        ull o0 = __shfl_xor_sync(0xffffffffu, acc[r][0], 16);
        ull o1 = __shfl_xor_sync(0xffffffffu, acc[r][1], 16);
        add2(acc[r][0], o0);
        add2(acc[r][1], o1);
    }

    __syncthreads();                              // x tile no longer needed
    if (half == 0) {
        #pragma unroll
        for (int r = 0; r < 16; r++)
            *reinterpret_cast<ulonglong2*>(&buf[wid * 1024 + r * 64 + hl]) =
                make_ulonglong2(acc[r][0], acc[r][1]);
    }
    __syncthreads();

    // ---- reduce 8 warp partials; thread owns 4 consecutive outputs ----
    {
        const int o = tid * 4;                    // o = r*64 + h, h%4==0
        const int r = o >> 6;
        const int h = o & 63;
        float4 s = make_float4(0.f, 0.f, 0.f, 0.f);
        #pragma unroll
        for (int w = 0; w < 8; w++) {
            float4 p = *reinterpret_cast<const float4*>(&buf[w * 1024 + o]);
            s.x += p.x; s.y += p.y; s.z += p.z; s.w += p.w;
        }

        const int row = r0 + r;
        if (mode == 0) {
            float4 bv = *reinterpret_cast<const float4*>(b1i + h);
            s.x += bv.x; s.y += bv.y; s.z += bv.z; s.w += bv.w;
            const int b = row >> 9, t = row & 511;
            float* dst = g_ctxT + ((size_t)(b << 6)) * 512 + t;
            dst[(h + 0) * 512] = s.x;
            dst[(h + 1) * 512] = s.y;
            dst[(h + 2) * 512] = s.z;
            dst[(h + 3) * 512] = s.w;
        } else if (mode == 1) {
            float4 bv = *reinterpret_cast<const float4*>(b1h + h);
            s.x += bv.x; s.y += bv.y; s.z += bv.z; s.w += bv.w;
            *reinterpret_cast<float4*>(&g_decS0[(size_t)row * 64 + h]) = s;
        } else {
            *reinterpret_cast<float4*>(&g_decS1[(size_t)row * 64 + h]) = s;
        }
    }
}

// ---------------------------------------------------------------------------
// Kernel B: fused tanh-score + softmax (R13 gold; prologue sums decS0+decS1).
// grid = 296 (4 batches x 74 d-tiles of 7) => 2 blocks/SM, 512 threads.
// ---------------------------------------------------------------------------
__global__ __launch_bounds__(512) void kernelB(
    const float* __restrict__ w2,    // [64]
    float* __restrict__ out)         // [4,512,512]
{
    __shared__ float dec_sh[7 * 64];
    __shared__ float w2_sh[64];      // pre-scaled by log2(e)
    __shared__ float red[7 * 16];
    __shared__ float inv_sh[7];

    const int tid = threadIdx.x;
    const int b   = blockIdx.x / 74;
    const int ti  = blockIdx.x % 74;
    const int d0  = ti * 7;

    // load decoder tile (sum of e-halves; zero past batch end) + w2*log2e
    if (tid < 448) {
        int r = tid >> 6;
        size_t idx = ((size_t)(b << 9) + d0) * 64 + tid;
        dec_sh[tid] = (d0 + r < 512) ? (g_decS0[idx] + g_decS1[idx]) : 0.f;
    } else {
        w2_sh[tid - 448] = w2[tid - 448] * LOG2E;
    }
    __syncthreads();

    const float* cptr = g_ctxT + (size_t)(b << 6) * 512 + tid;

    float acc[7];
    #pragma unroll
    for (int d = 0; d < 7; d++) acc[d] = 0.f;

    // prime the pipeline with h-group 0
    float c0 = cptr[0 * 512];
    float c1 = cptr[1 * 512];
    float c2 = cptr[2 * 512];
    float c3 = cptr[3 * 512];

    #pragma unroll 1
    for (int h = 0; h < 64; h += 4) {
        // prefetch next group (wrap &63 on last iter: in-bounds, unused)
        const int hn = (h + 4) & 63;
        float n0 = cptr[(hn + 0) * 512];
        float n1 = cptr[(hn + 1) * 512];
        float n2 = cptr[(hn + 2) * 512];
        float n3 = cptr[(hn + 3) * 512];

        float4 w4 = *reinterpret_cast<const float4*>(&w2_sh[h]);
        #pragma unroll
        for (int d = 0; d < 7; d++) {
            float4 dv = *reinterpret_cast<const float4*>(&dec_sh[d * 64 + h]);
            acc[d] = fmaf(w4.x, tanh_approx(dv.x + c0), acc[d]);
            acc[d] = fmaf(w4.y, tanh_approx(dv.y + c1), acc[d]);
            acc[d] = fmaf(w4.z, tanh_approx(dv.z + c2), acc[d]);
            acc[d] = fmaf(w4.w, tanh_approx(dv.w + c3), acc[d]);
        }
        c0 = n0; c1 = n1; c2 = n2; c3 = n3;
    }

    // softmax over t (acc in log2 domain; b2 cancels; scores bounded by
    // sum|w2|*log2e ~ 9 => no max-shift needed)
    const int wid = tid >> 5, lane = tid & 31;
    float ex[7];
    #pragma unroll
    for (int d = 0; d < 7; d++) {
        float e = ex2_approx(acc[d]);
        ex[d] = e;
        float s = e;
        #pragma unroll
        for (int off = 16; off; off >>= 1)
            s += __shfl_xor_sync(0xffffffffu, s, off);
        if (lane == 0) red[d * 16 + wid] = s;
    }
    __syncthreads();
    if (wid < 7) {
        float v = (lane < 16) ? red[wid * 16 + lane] : 0.f;
        #pragma unroll
        for (int off = 8; off; off >>= 1)
            v += __shfl_xor_sync(0xffffffffu, v, off);
        if (lane == 0) inv_sh[wid] = 1.0f / v;
    }
    __syncthreads();
    #pragma unroll
    for (int d = 0; d < 7; d++) {
        if (d0 + d < 512)
            out[((size_t)(b << 9) + d0 + d) * 512 + tid] = ex[d] * inv_sh[d];
    }
}

// ---------------------------------------------------------------------------
extern "C" void kernel_launch(void* const* d_in, const int* in_sizes, int n_in,
                              void* d_out, int out_size)
{
    const float* ctx  = (const float*)d_in[0];
    const float* dec  = (const float*)d_in[1];
    const float* W1i  = (const float*)d_in[2];
    const float* b1i  = (const float*)d_in[3];
    const float* W1h  = (const float*)d_in[4];
    const float* b1h  = (const float*)d_in[5];
    const float* w2   = (const float*)d_in[6];
    float* out = (float*)d_out;

    kernelA<<<384, 256>>>(ctx, dec, W1i, b1i, W1h, b1h);
    kernelB<<<296, 512>>>(w2, out);
}